// round 7
// baseline (speedup 1.0000x reference)
#include <cuda_runtime.h>
#include <cstdint>

#define NQ    65536
#define BQ    256
#define HIDQ  64
#define TPB   128
#define TILE  512
#define RROWS 8
#define SCAP  264   // c3 ~ Binom(512,1/4): mean 128, sigma 9.8; inline fallback guards rest

__device__ __forceinline__ float tanhax(float x) {
    float y; asm("tanh.approx.f32 %0, %1;" : "=f"(y) : "f"(x)); return y;
}

__global__ __launch_bounds__(TPB, 12) void soen_kernel(
    const float* __restrict__ phi, const float* __restrict__ s,
    const float* __restrict__ i_b, const float* __restrict__ w1,
    const float* __restrict__ b1,  const float* __restrict__ w2,
    const float* __restrict__ b2,  const int* __restrict__ fidx,
    float* __restrict__ out)
{
    __shared__ float4 q4[HIDQ];            // (w1[0][k], w1[1][k], w1[2][k], b1[k])
    __shared__ float  vv[HIDQ];            // w2[k] (read as float4)
    __shared__ int    cnt3;
    __shared__ int    col3[SCAP];
    __shared__ float  ib3[SCAP];
    __shared__ float  st_p[RROWS][SCAP];   // func3 stash: periodic(phi)
    __shared__ float  st_s[RROWS][SCAP];   // func3 stash: s

    const int t        = threadIdx.x;
    const int lane     = t & 31;
    const int tileBase = blockIdx.x * TILE;
    const int r0       = blockIdx.y * RROWS;

    if (t < HIDQ) {
        q4[t] = make_float4(w1[t], w1[HIDQ + t], w1[2 * HIDQ + t], b1[t]);
        vv[t] = w2[t];
    }
    if (t == 0) cnt3 = 0;
    __syncthreads();

    // ---- compaction: func3 columns (thread t owns cols 4t..4t+3) ----
    const int4 fi4 = ((const int4*)(fidx + tileBase))[t];
    int f[4] = {fi4.x, fi4.y, fi4.z, fi4.w};
    int myrank[4];
#pragma unroll
    for (int e = 0; e < 4; e++) {
        const unsigned mask = __ballot_sync(0xffffffffu, f[e] == 3);
        int rank = -1;
        if (mask) {
            const int leader = __ffs(mask) - 1;
            int base = 0;
            if (lane == leader) base = atomicAdd(&cnt3, __popc(mask));
            base = __shfl_sync(0xffffffffu, base, leader);
            if (f[e] == 3) {
                rank = base + __popc(mask & ((1u << lane) - 1u));
                if (rank < SCAP) {
                    const int lc = 4 * t + e;
                    col3[rank] = lc;
                    ib3[rank]  = i_b[tileBase + lc];
                }
            }
        }
        myrank[e] = rank;
    }
    __syncthreads();
    const int   c3    = cnt3;
    const float bias2 = b2[0];

    // ---- Phase A: stream rows; cheap funcs direct-stored; func3 (p,s) stashed ----
    for (int rr = 0; rr < RROWS; rr++) {
        const size_t rowOff = (size_t)(r0 + rr) * NQ + tileBase;
        const float4 ph4 = ((const float4*)(phi + rowOff))[t];
        const float4 sv4 = ((const float4*)(s   + rowOff))[t];
        const float phv[4] = {ph4.x, ph4.y, ph4.z, ph4.w};
        const float svv[4] = {sv4.x, sv4.y, sv4.z, sv4.w};
#pragma unroll
        for (int e = 0; e < 4; e++) {
            const float p  = phv[e] - rintf(phv[e]);
            const float sv = svv[e];
            if (f[e] == 3) {
                const int rk = myrank[e];
                if (rk < SCAP) {
                    st_p[rr][rk] = p; st_s[rr][rk] = sv;
                } else {  // cold overflow fallback: inline MLP
                    const float ibv = i_b[tileBase + 4 * t + e];
                    float acc = bias2;
                    for (int k = 0; k < HIDQ; k++) {
                        const float4 w = q4[k];
                        const float  z = fmaf(p, w.x, fmaf(sv, w.y, fmaf(ibv, w.z, w.w)));
                        acc = fmaf(tanhax(z), vv[k], acc);
                    }
                    out[rowOff + 4 * t + e] = acc;
                }
            } else {
                const float g0 = fmaxf(fabsf(p) - sv, 0.0f);
                const float g1 = tanhax(p) * (1.0f - sv);
                const float g2 = exp2f(p * p * (-14.4269504088896340736f)) - sv;
                out[rowOff + 4 * t + e] = (f[e] == 0) ? g0 : ((f[e] == 1) ? g1 : g2);
            }
        }
    }
    __syncthreads();

    // ---- Phase B: item = (func3 column) x (2-row slice); 4*ccap items ----
    const int ccap  = (c3 < SCAP) ? c3 : SCAP;
    const int items = 4 * ccap;
    for (int j = t; j < items; j += TPB) {
        int col = j, rb = 0;
        while (col >= ccap) { col -= ccap; rb += 2; }
        const int   lc  = col3[col];
        const float ibv = ib3[col];

        float p0 = st_p[rb][col],     s0 = st_s[rb][col];
        float p1 = st_p[rb + 1][col], s1 = st_s[rb + 1][col];
        float a0 = bias2, a1 = bias2;

#pragma unroll 4
        for (int k = 0; k < HIDQ; k += 4) {
            const float4 v4 = ((const float4*)vv)[k >> 2];
            const float  vva[4] = {v4.x, v4.y, v4.z, v4.w};
#pragma unroll
            for (int kk = 0; kk < 4; kk++) {
                const float4 w  = q4[k + kk];
                const float  ck = fmaf(ibv, w.z, w.w);
                const float  v  = vva[kk];
                const float z0 = fmaf(p0, w.x, fmaf(s0, w.y, ck));
                const float z1 = fmaf(p1, w.x, fmaf(s1, w.y, ck));
                a0 = fmaf(tanhax(z0), v, a0);
                a1 = fmaf(tanhax(z1), v, a1);
            }
        }

        const size_t base = (size_t)(r0 + rb) * NQ + tileBase + lc;
        out[base]      = a0;
        out[base + NQ] = a1;
    }
}

extern "C" void kernel_launch(void* const* d_in, const int* in_sizes, int n_in,
                              void* d_out, int out_size)
{
    const float* phi  = (const float*)d_in[0];
    const float* s    = (const float*)d_in[1];
    const float* i_b  = (const float*)d_in[2];
    const float* w1   = (const float*)d_in[3];
    const float* b1   = (const float*)d_in[4];
    const float* w2   = (const float*)d_in[5];
    const float* b2   = (const float*)d_in[6];
    const int*   fidx = (const int*)d_in[7];
    float*       out  = (float*)d_out;

    dim3 grid(NQ / TILE, BQ / RROWS);   // (128, 32) = 4096 blocks of 128 threads
    soen_kernel<<<grid, TPB>>>(phi, s, i_b, w1, b1, w2, b2, fidx, out);
}

// round 12
// speedup vs baseline: 1.6584x; 1.6584x over previous
#include <cuda_runtime.h>
#include <cuda_fp16.h>
#include <cstdint>

#define NQ    65536
#define BQ    256
#define HIDQ  64
#define TPB   128
#define TILE  512
#define RROWS 8
#define SCAP  264   // c3 ~ Binom(512,1/4): mean 128, sigma 9.8; inline fallback guards rest

__device__ __forceinline__ float tanhax(float x) {
    float y; asm("tanh.approx.f32 %0, %1;" : "=f"(y) : "f"(x)); return y;
}

// two tanh for one MUFU issue: f32 in -> f16x2 tanh -> f32 out
__device__ __forceinline__ float2 tanh2f(float z0, float z1) {
    __half2 h = __floats2half2_rn(z0, z1);
    unsigned u = *reinterpret_cast<unsigned*>(&h);
    asm("tanh.approx.f16x2 %0, %0;" : "+r"(u));
    h = *reinterpret_cast<__half2*>(&u);
    return __half22float2(h);
}

__global__ __launch_bounds__(TPB) void soen_kernel(
    const float* __restrict__ phi, const float* __restrict__ s,
    const float* __restrict__ i_b, const float* __restrict__ w1,
    const float* __restrict__ b1,  const float* __restrict__ w2,
    const float* __restrict__ b2,  const int* __restrict__ fidx,
    float* __restrict__ out)
{
    __shared__ float4 q4[HIDQ];            // (w1[0][k], w1[1][k], w1[2][k], b1[k])
    __shared__ float  vv[HIDQ];            // w2[k]
    __shared__ int    cnt3;
    __shared__ int    col3[SCAP];
    __shared__ float  ib3[SCAP];
    __shared__ float  st_p[RROWS][SCAP];   // func3 stash: periodic(phi)
    __shared__ float  st_s[RROWS][SCAP];   // func3 stash: s

    const int t        = threadIdx.x;
    const int lane     = t & 31;
    const int tileBase = blockIdx.x * TILE;
    const int r0       = blockIdx.y * RROWS;

    if (t < HIDQ) {
        q4[t] = make_float4(w1[t], w1[HIDQ + t], w1[2 * HIDQ + t], b1[t]);
        vv[t] = w2[t];
    }
    if (t == 0) cnt3 = 0;
    __syncthreads();

    // ---- compaction: func3 columns (thread t owns cols 4t..4t+3) ----
    const int4 fi4 = ((const int4*)(fidx + tileBase))[t];
    int f[4] = {fi4.x, fi4.y, fi4.z, fi4.w};
    int myrank[4];
#pragma unroll
    for (int e = 0; e < 4; e++) {
        const unsigned mask = __ballot_sync(0xffffffffu, f[e] == 3);
        int rank = -1;
        if (mask) {
            const int leader = __ffs(mask) - 1;
            int base = 0;
            if (lane == leader) base = atomicAdd(&cnt3, __popc(mask));
            base = __shfl_sync(0xffffffffu, base, leader);
            if (f[e] == 3) {
                rank = base + __popc(mask & ((1u << lane) - 1u));
                if (rank < SCAP) {
                    const int lc = 4 * t + e;
                    col3[rank] = lc;
                    ib3[rank]  = i_b[tileBase + lc];
                }
            }
        }
        myrank[e] = rank;
    }
    __syncthreads();
    const int   c3    = cnt3;
    const float bias2 = b2[0];

    // ---- Phase A: stream rows; cheap funcs direct-stored; func3 (p,s) stashed ----
    for (int rr = 0; rr < RROWS; rr++) {
        const size_t rowOff = (size_t)(r0 + rr) * NQ + tileBase;
        const float4 ph4 = ((const float4*)(phi + rowOff))[t];
        const float4 sv4 = ((const float4*)(s   + rowOff))[t];
        const float phv[4] = {ph4.x, ph4.y, ph4.z, ph4.w};
        const float svv[4] = {sv4.x, sv4.y, sv4.z, sv4.w};
#pragma unroll
        for (int e = 0; e < 4; e++) {
            const float p  = phv[e] - rintf(phv[e]);
            const float sv = svv[e];
            if (f[e] == 3) {
                const int rk = myrank[e];
                if (rk < SCAP) {
                    st_p[rr][rk] = p; st_s[rr][rk] = sv;
                } else {  // cold overflow fallback: full-precision inline MLP
                    const float ibv = i_b[tileBase + 4 * t + e];
                    float acc = bias2;
                    for (int k = 0; k < HIDQ; k++) {
                        const float4 w = q4[k];
                        const float  z = fmaf(p, w.x, fmaf(sv, w.y, fmaf(ibv, w.z, w.w)));
                        acc = fmaf(tanhax(z), vv[k], acc);
                    }
                    out[rowOff + 4 * t + e] = acc;
                }
            } else {
                const float g0 = fmaxf(fabsf(p) - sv, 0.0f);
                const float g1 = tanhax(p) * (1.0f - sv);
                const float g2 = exp2f(p * p * (-14.4269504088896340736f)) - sv;
                out[rowOff + 4 * t + e] = (f[e] == 0) ? g0 : ((f[e] == 1) ? g1 : g2);
            }
        }
    }
    __syncthreads();

    // ---- Phase B: item = (func3 column) x (4-row slice); f16x2 tanh (2 rows per MUFU) ----
    const int ccap  = (c3 < SCAP) ? c3 : SCAP;
    const int items = 2 * ccap;
    for (int j = t; j < items; j += TPB) {
        const int col   = (j < ccap) ? j : (j - ccap);
        const int rb    = (j < ccap) ? 0 : 4;
        const int lc    = col3[col];
        const float ibv = ib3[col];

        float p[4], sv[4], acc[4];
#pragma unroll
        for (int i = 0; i < 4; i++) {
            p[i]   = st_p[rb + i][col];
            sv[i]  = st_s[rb + i][col];
            acc[i] = bias2;
        }

#pragma unroll 8
        for (int k = 0; k < HIDQ; k++) {
            const float4 w  = q4[k];       // uniform-address LDS (broadcast)
            const float  ck = fmaf(ibv, w.z, w.w);
            const float  v  = vv[k];
            const float z0 = fmaf(p[0], w.x, fmaf(sv[0], w.y, ck));
            const float z1 = fmaf(p[1], w.x, fmaf(sv[1], w.y, ck));
            const float z2 = fmaf(p[2], w.x, fmaf(sv[2], w.y, ck));
            const float z3 = fmaf(p[3], w.x, fmaf(sv[3], w.y, ck));
            const float2 h01 = tanh2f(z0, z1);
            const float2 h23 = tanh2f(z2, z3);
            acc[0] = fmaf(h01.x, v, acc[0]);
            acc[1] = fmaf(h01.y, v, acc[1]);
            acc[2] = fmaf(h23.x, v, acc[2]);
            acc[3] = fmaf(h23.y, v, acc[3]);
        }

        const size_t base = (size_t)(r0 + rb) * NQ + tileBase + lc;
#pragma unroll
        for (int i = 0; i < 4; i++)
            out[base + (size_t)i * NQ] = acc[i];
    }
}

extern "C" void kernel_launch(void* const* d_in, const int* in_sizes, int n_in,
                              void* d_out, int out_size)
{
    const float* phi  = (const float*)d_in[0];
    const float* s    = (const float*)d_in[1];
    const float* i_b  = (const float*)d_in[2];
    const float* w1   = (const float*)d_in[3];
    const float* b1   = (const float*)d_in[4];
    const float* w2   = (const float*)d_in[5];
    const float* b2   = (const float*)d_in[6];
    const int*   fidx = (const int*)d_in[7];
    float*       out  = (float*)d_out;

    dim3 grid(NQ / TILE, BQ / RROWS);   // (128, 32) = 4096 blocks of 128 threads
    soen_kernel<<<grid, TPB>>>(phi, s, i_b, w1, b1, w2, b2, fidx, out);
}

// round 13
// speedup vs baseline: 1.6828x; 1.0147x over previous
#include <cuda_runtime.h>
#include <cuda_fp16.h>
#include <cstdint>

#define NQ    65536
#define BQ    256
#define HIDQ  64
#define TPB   128
#define TILE  512
#define RROWS 8
#define SCAP  264   // c3 ~ Binom(512,1/4): mean 128, sigma 9.8; inline fallback guards rest

__device__ __forceinline__ float tanhax(float x) {
    float y; asm("tanh.approx.f32 %0, %1;" : "=f"(y) : "f"(x)); return y;
}

// two tanh for one MUFU issue: f32 in -> f16x2 tanh -> f32 out
__device__ __forceinline__ float2 tanh2f(float z0, float z1) {
    __half2 h = __floats2half2_rn(z0, z1);
    unsigned u = *reinterpret_cast<unsigned*>(&h);
    asm("tanh.approx.f16x2 %0, %0;" : "+r"(u));
    h = *reinterpret_cast<__half2*>(&u);
    return __half22float2(h);
}

__global__ __launch_bounds__(TPB) void soen_kernel(
    const float* __restrict__ phi, const float* __restrict__ s,
    const float* __restrict__ i_b, const float* __restrict__ w1,
    const float* __restrict__ b1,  const float* __restrict__ w2,
    const float* __restrict__ b2,  const int* __restrict__ fidx,
    float* __restrict__ out)
{
    __shared__ float4 q4[HIDQ];            // (w1[0][k], w1[1][k], w1[2][k], b1[k])
    __shared__ float  vv[HIDQ];            // w2[k]
    __shared__ int    cnt3;
    __shared__ int    col3[SCAP];
    __shared__ float  ib3[SCAP];
    __shared__ float  st_p[RROWS][SCAP];   // func3 stash: periodic(phi)
    __shared__ float  st_s[RROWS][SCAP];   // func3 stash: s

    const int t        = threadIdx.x;
    const int lane     = t & 31;
    const int tileBase = blockIdx.x * TILE;
    const int r0       = blockIdx.y * RROWS;

    if (t < HIDQ) {
        q4[t] = make_float4(w1[t], w1[HIDQ + t], w1[2 * HIDQ + t], b1[t]);
        vv[t] = w2[t];
    }
    if (t == 0) cnt3 = 0;
    __syncthreads();

    // ---- compaction: func3 columns (thread t owns cols 4t..4t+3) ----
    const int4 fi4 = ((const int4*)(fidx + tileBase))[t];
    int f[4] = {fi4.x, fi4.y, fi4.z, fi4.w};
    int myrank[4];
#pragma unroll
    for (int e = 0; e < 4; e++) {
        const unsigned mask = __ballot_sync(0xffffffffu, f[e] == 3);
        int rank = -1;
        if (mask) {
            const int leader = __ffs(mask) - 1;
            int base = 0;
            if (lane == leader) base = atomicAdd(&cnt3, __popc(mask));
            base = __shfl_sync(0xffffffffu, base, leader);
            if (f[e] == 3) {
                rank = base + __popc(mask & ((1u << lane) - 1u));
                if (rank < SCAP) {
                    const int lc = 4 * t + e;
                    col3[rank] = lc;
                    ib3[rank]  = i_b[tileBase + lc];
                }
            }
        }
        myrank[e] = rank;
    }
    __syncthreads();
    const int   c3    = cnt3;
    const float bias2 = b2[0];

    // ---- Phase A: row-serial (unroll 1) to avoid LDG front-batching:
    //      keeps MLP_p1 low (kills cross-CTA L1tex-queue spread before the barrier)
    //      and keeps register liveness small for higher occupancy.
#pragma unroll 1
    for (int rr = 0; rr < RROWS; rr++) {
        const size_t rowOff = (size_t)(r0 + rr) * NQ + tileBase;
        const float4 ph4 = ((const float4*)(phi + rowOff))[t];
        const float4 sv4 = ((const float4*)(s   + rowOff))[t];
        const float phv[4] = {ph4.x, ph4.y, ph4.z, ph4.w};
        const float svv[4] = {sv4.x, sv4.y, sv4.z, sv4.w};
#pragma unroll
        for (int e = 0; e < 4; e++) {
            const float p  = phv[e] - rintf(phv[e]);
            const float sv = svv[e];
            if (f[e] == 3) {
                const int rk = myrank[e];
                if (rk < SCAP) {
                    st_p[rr][rk] = p; st_s[rr][rk] = sv;
                } else {  // cold overflow fallback: full-precision inline MLP
                    const float ibv = i_b[tileBase + 4 * t + e];
                    float acc = bias2;
                    for (int k = 0; k < HIDQ; k++) {
                        const float4 w = q4[k];
                        const float  z = fmaf(p, w.x, fmaf(sv, w.y, fmaf(ibv, w.z, w.w)));
                        acc = fmaf(tanhax(z), vv[k], acc);
                    }
                    out[rowOff + 4 * t + e] = acc;
                }
            } else {
                const float g0 = fmaxf(fabsf(p) - sv, 0.0f);
                const float g1 = tanhax(p) * (1.0f - sv);
                const float g2 = exp2f(p * p * (-14.4269504088896340736f)) - sv;
                out[rowOff + 4 * t + e] = (f[e] == 0) ? g0 : ((f[e] == 1) ? g1 : g2);
            }
        }
    }
    __syncthreads();

    // ---- Phase B: item = (func3 column) x (4-row slice); f16x2 tanh (2 rows per MUFU) ----
    const int ccap  = (c3 < SCAP) ? c3 : SCAP;
    const int items = 2 * ccap;
    for (int j = t; j < items; j += TPB) {
        const int col   = (j < ccap) ? j : (j - ccap);
        const int rb    = (j < ccap) ? 0 : 4;
        const int lc    = col3[col];
        const float ibv = ib3[col];

        float p[4], sv[4], acc[4];
#pragma unroll
        for (int i = 0; i < 4; i++) {
            p[i]   = st_p[rb + i][col];
            sv[i]  = st_s[rb + i][col];
            acc[i] = bias2;
        }

#pragma unroll 8
        for (int k = 0; k < HIDQ; k++) {
            const float4 w  = q4[k];       // uniform-address LDS (broadcast)
            const float  ck = fmaf(ibv, w.z, w.w);
            const float  v  = vv[k];
            const float z0 = fmaf(p[0], w.x, fmaf(sv[0], w.y, ck));
            const float z1 = fmaf(p[1], w.x, fmaf(sv[1], w.y, ck));
            const float z2 = fmaf(p[2], w.x, fmaf(sv[2], w.y, ck));
            const float z3 = fmaf(p[3], w.x, fmaf(sv[3], w.y, ck));
            const float2 h01 = tanh2f(z0, z1);
            const float2 h23 = tanh2f(z2, z3);
            acc[0] = fmaf(h01.x, v, acc[0]);
            acc[1] = fmaf(h01.y, v, acc[1]);
            acc[2] = fmaf(h23.x, v, acc[2]);
            acc[3] = fmaf(h23.y, v, acc[3]);
        }

        const size_t base = (size_t)(r0 + rb) * NQ + tileBase + lc;
#pragma unroll
        for (int i = 0; i < 4; i++)
            out[base + (size_t)i * NQ] = acc[i];
    }
}

extern "C" void kernel_launch(void* const* d_in, const int* in_sizes, int n_in,
                              void* d_out, int out_size)
{
    const float* phi  = (const float*)d_in[0];
    const float* s    = (const float*)d_in[1];
    const float* i_b  = (const float*)d_in[2];
    const float* w1   = (const float*)d_in[3];
    const float* b1   = (const float*)d_in[4];
    const float* w2   = (const float*)d_in[5];
    const float* b2   = (const float*)d_in[6];
    const int*   fidx = (const int*)d_in[7];
    float*       out  = (float*)d_out;

    dim3 grid(NQ / TILE, BQ / RROWS);   // (128, 32) = 4096 blocks of 128 threads
    soen_kernel<<<grid, TPB>>>(phi, s, i_b, w1, b1, w2, b2, fidx, out);
}